// round 1
// baseline (speedup 1.0000x reference)
#include <cuda_runtime.h>

// RNN_64501818851829 — persistent fp32x2 SIMT RNN for GB300 (sm_103a)
//
// Shapes: B=4096 rows, T=1024 steps, hidden H=40, combined K1=41.
// Each block owns 16 rows (8 f32x2 "pairs") for the entire T loop.
// Weights are pre-duplicated f32x2 in shared memory ([k][j]-major) so the
// inner dot is: 1 LDS.64 (combined, broadcast) + 2 LDS.128 (4 dup weights)
// + 4 fma.rn.f32x2  => fma-pipe-bound at ~128 FMA/cyc/SM.

typedef unsigned long long u64;

static constexpr int Bn = 4096;
static constexpr int Tn = 1024;
static constexpr int PAIRS = 8;            // row-pairs per block (16 rows)
static constexpr int JG = 20;              // neuron groups (NJ=4 neurons each)
static constexpr int NTHR = PAIRS * JG;    // 160 threads
static constexpr int NBLK = (Bn / 2) / PAIRS;  // 256 blocks

// Scratch (no cudaMalloc allowed): transposed input [T][B] and output [T][B]
__device__ float g_uT[Tn * Bn];
__device__ float g_outT[Tn * Bn];

// ---------------- f32x2 helpers ----------------
__device__ __forceinline__ u64 fma2(u64 a, u64 b, u64 c) {
    u64 d; asm("fma.rn.f32x2 %0, %1, %2, %3;" : "=l"(d) : "l"(a), "l"(b), "l"(c));
    return d;
}
__device__ __forceinline__ u64 add2(u64 a, u64 b) {
    u64 d; asm("add.rn.f32x2 %0, %1, %2;" : "=l"(d) : "l"(a), "l"(b));
    return d;
}
__device__ __forceinline__ u64 mul2(u64 a, u64 b) {
    u64 d; asm("mul.rn.f32x2 %0, %1, %2;" : "=l"(d) : "l"(a), "l"(b));
    return d;
}
__device__ __forceinline__ u64 pack2(float lo, float hi) {
    u64 d; asm("mov.b64 %0, {%1, %2};" : "=l"(d) : "f"(lo), "f"(hi));
    return d;
}
__device__ __forceinline__ void unpack2(u64 v, float& lo, float& hi) {
    asm("mov.b64 {%0, %1}, %2;" : "=f"(lo), "=f"(hi) : "l"(v));
}
__device__ __forceinline__ u64 dup2(float x) { return pack2(x, x); }
__device__ __forceinline__ u64 lrelu2(u64 x) {
    float a, b; unpack2(x, a, b);
    a = fmaxf(a, 0.0f) + 0.01f * fminf(a, 0.0f);
    b = fmaxf(b, 0.0f) + 0.01f * fminf(b, 0.0f);
    return pack2(a, b);
}

// ---------------- transpose kernels ----------------
// in: inputs [B][T] -> g_uT [T][B]
__global__ void tpose_in_kernel(const float* __restrict__ src) {
    __shared__ float tile[32][33];
    int c0 = blockIdx.x * 32, r0 = blockIdx.y * 32;   // c over T, r over B
    int x = c0 + threadIdx.x;
#pragma unroll
    for (int i = threadIdx.y; i < 32; i += 8)
        tile[i][threadIdx.x] = src[(size_t)(r0 + i) * Tn + x];
    __syncthreads();
    int y = r0 + threadIdx.x;
#pragma unroll
    for (int i = threadIdx.y; i < 32; i += 8)
        g_uT[(size_t)(c0 + i) * Bn + y] = tile[threadIdx.x][i];
}

// out: g_outT [T][B] -> d_out [B][T]
__global__ void tpose_out_kernel(float* __restrict__ dst) {
    __shared__ float tile[32][33];
    int c0 = blockIdx.x * 32, r0 = blockIdx.y * 32;   // c over B, r over T
    int x = c0 + threadIdx.x;
#pragma unroll
    for (int i = threadIdx.y; i < 32; i += 8)
        tile[i][threadIdx.x] = g_outT[(size_t)(r0 + i) * Bn + x];
    __syncthreads();
    int y = r0 + threadIdx.x;
#pragma unroll
    for (int i = threadIdx.y; i < 32; i += 8)
        dst[(size_t)(c0 + i) * Tn + y] = tile[threadIdx.x][i];
}

// ---------------- main persistent RNN kernel ----------------
__global__ void __launch_bounds__(NTHR, 2) rnn_kernel(
    const float* __restrict__ w1,  const float* __restrict__ b1,
    const float* __restrict__ w2,  const float* __restrict__ b2,
    const float* __restrict__ ow1, const float* __restrict__ ob1,
    const float* __restrict__ ow2, const float* __restrict__ ob2)
{
    // L1 weights combined: j<40 -> h2h_w1 row j; j in [40,80) -> h2o_w1 row j-40
    __shared__ __align__(16) u64 shWc[41 * 80];       // [k][j] dup   26240 B
    __shared__ __align__(16) u64 shW2[40 * 40];       // [k][j] dup   12800 B
    __shared__ __align__(16) u64 shComb[PAIRS * 42];  // [p]: [1]=u, [2..41]=hidden
    __shared__ __align__(16) u64 shA[PAIRS * 42];     // h2h L1 activations
    __shared__ __align__(16) u64 shPart[PAIRS * 42];  // L2 upper-half partials
    __shared__ __align__(16) u64 shOutp[PAIRS * 12];  // output-dot partials (10)

    const int tid  = threadIdx.x;
    const int pair = tid & (PAIRS - 1);
    const int jg   = tid >> 3;          // 0..19
    const bool islo = (jg < 10);
    const int jj   = islo ? jg : jg - 10;
    const int n0   = 4 * jj;
    const int row0 = 2 * (blockIdx.x * PAIRS + pair);

    // Cooperative weight load with duplication into f32x2
    for (int idx = tid; idx < 41 * 80; idx += NTHR) {
        int k = idx / 80, j = idx % 80;
        float w = (j < 40) ? w1[j * 41 + k] : ow1[(j - 40) * 41 + k];
        shWc[idx] = dup2(w);
    }
    for (int idx = tid; idx < 40 * 40; idx += NTHR) {
        int k = idx / 40, j = idx % 40;
        shW2[idx] = dup2(w2[j * 40 + k]);
    }
    for (int idx = tid; idx < PAIRS * 42; idx += NTHR) shComb[idx] = 0ull;

    // Per-thread constants in registers
    u64 rb1[4], rX[4];
    if (islo) {
#pragma unroll
        for (int i = 0; i < 4; i++) { rb1[i] = dup2(b1[n0 + i]); rX[i] = dup2(b2[n0 + i]); }
    } else {
#pragma unroll
        for (int i = 0; i < 4; i++) { rb1[i] = dup2(ob1[n0 + i]); rX[i] = dup2(ow2[n0 + i]); }
    }
    const u64 bout = dup2(ob2[0]);

    __syncthreads();
    if (jg == 1) shComb[pair * 42 + 1] = *(const u64*)&g_uT[row0];  // u at t=0

    const u64* __restrict__ cb = shComb + pair * 42 + 1;
    const u64* __restrict__ ap = shA + pair * 42 + (islo ? 0 : 20);
    const u64* __restrict__ w2base = shW2 + (islo ? 0 : 20) * 40 + 4 * jj;

    u64 uNext = 0ull;
    for (int t = 0; t < Tn; t++) {
        __syncthreads();  // combined[t] ready

        // ---- L1: 80 neurons x dot-41 (this thread: 4 neurons) ----
        u64 a0 = rb1[0], a1 = rb1[1], a2 = rb1[2], a3 = rb1[3];
#pragma unroll
        for (int k = 0; k < 41; k++) {
            u64 c = cb[k];
            const ulonglong2* w = (const ulonglong2*)(shWc + k * 80 + 4 * jg);
            ulonglong2 wA = w[0], wB = w[1];
            a0 = fma2(c, wA.x, a0); a1 = fma2(c, wA.y, a1);
            a2 = fma2(c, wB.x, a2); a3 = fma2(c, wB.y, a3);
        }
        a0 = lrelu2(a0); a1 = lrelu2(a1); a2 = lrelu2(a2); a3 = lrelu2(a3);

        if (jg == 1)  // prefetch next step's input
            uNext = (t + 1 < Tn) ? *(const u64*)&g_uT[(t + 1) * Bn + row0] : 0ull;

        if (islo) {   // h2h activations -> shared for L2
            ulonglong2* d = (ulonglong2*)(shA + pair * 42 + 4 * jg);
            d[0] = make_ulonglong2(a0, a1);
            d[1] = make_ulonglong2(a2, a3);
        } else {      // h2o: local partial of the 40-wide output dot
            u64 s = mul2(a3, rX[3]);
            s = fma2(a2, rX[2], s);
            s = fma2(a1, rX[1], s);
            s = fma2(a0, rX[0], s);
            shOutp[pair * 12 + jj] = s;
        }
        __syncthreads();  // acts + out-partials ready

        // ---- L2: hidden_new (40 x dot-40), split lower/upper k halves ----
        u64 h0, h1, h2, h3;
        if (islo) { h0 = rX[0]; h1 = rX[1]; h2 = rX[2]; h3 = rX[3]; }
        else      { h0 = h1 = h2 = h3 = 0ull; }
#pragma unroll
        for (int k = 0; k < 20; k++) {
            u64 av = ap[k];
            const ulonglong2* w = (const ulonglong2*)(w2base + k * 40);
            ulonglong2 wA = w[0], wB = w[1];
            h0 = fma2(av, wA.x, h0); h1 = fma2(av, wA.y, h1);
            h2 = fma2(av, wB.x, h2); h3 = fma2(av, wB.y, h3);
        }
        if (!islo) {
            ulonglong2* d = (ulonglong2*)(shPart + pair * 42 + 4 * jj);
            d[0] = make_ulonglong2(h0, h1);
            d[1] = make_ulonglong2(h2, h3);
        }
        if (jg == 10) {  // reduce output partials, write out[t] for 2 rows
            u64 s = bout;
#pragma unroll
            for (int i = 0; i < 10; i++) s = add2(s, shOutp[pair * 12 + i]);
            *(u64*)&g_outT[t * Bn + row0] = s;
        }
        __syncthreads();  // upper partials ready

        if (islo) {       // combine halves -> hidden_new -> next combined
            const ulonglong2* q = (const ulonglong2*)(shPart + pair * 42 + 4 * jg);
            ulonglong2 q0 = q[0], q1 = q[1];
            ulonglong2* d = (ulonglong2*)(shComb + pair * 42 + 2 + 4 * jg);
            d[0] = make_ulonglong2(add2(h0, q0.x), add2(h1, q0.y));
            d[1] = make_ulonglong2(add2(h2, q1.x), add2(h3, q1.y));
        }
        if (jg == 1) shComb[pair * 42 + 1] = uNext;  // next u
    }
}

extern "C" void kernel_launch(void* const* d_in, const int* in_sizes, int n_in,
                              void* d_out, int out_size) {
    const float* inputs = (const float*)d_in[0];
    const float* w1  = (const float*)d_in[1];
    const float* b1  = (const float*)d_in[2];
    const float* w2  = (const float*)d_in[3];
    const float* b2  = (const float*)d_in[4];
    const float* ow1 = (const float*)d_in[5];
    const float* ob1 = (const float*)d_in[6];
    const float* ow2 = (const float*)d_in[7];
    const float* ob2 = (const float*)d_in[8];
    float* out = (float*)d_out;

    // 1) transpose inputs [B][T] -> g_uT [T][B]
    tpose_in_kernel<<<dim3(Tn / 32, Bn / 32), dim3(32, 8)>>>(inputs);
    // 2) persistent RNN over all T steps
    rnn_kernel<<<NBLK, NTHR>>>(w1, b1, w2, b2, ow1, ob1, ow2, ob2);
    // 3) transpose g_outT [T][B] -> out [B][T]
    tpose_out_kernel<<<dim3(Bn / 32, Tn / 32), dim3(32, 8)>>>(out);
}